// round 15
// baseline (speedup 1.0000x reference)
#include <cuda_runtime.h>
#include <cuda_fp16.h>
#include <math.h>

#define D 128
#define MAXN 100000
#define MAXE 3200000
#define TOPK 128
#define CANDCAP 4096
#define SCAN_CHUNK 1024

// ---------------- scratch ----------------------------------------------------
__device__ float    g_score[MAXN];
__device__ unsigned g_h16[65536];
__device__ unsigned g_thresh;
__device__ int      g_ncand;
__device__ int      g_cand_idx[CANDCAP];
__device__ unsigned g_cand_key[CANDCAP];
__device__ float    g_cand_val[CANDCAP];
__device__ float    g_W[D * D];
__device__ __half2  g_yh[(size_t)MAXN * 64];   // y = (x@W)*dinv[row], fp16
__device__ float    g_dinv[MAXN];
__device__ int      g_deg[MAXN];
__device__ int      g_off[MAXN + 1];
__device__ int      g_cur[MAXN];
__device__ int      g_bsum[1024];
__device__ int      g_er[MAXE];

__device__ __forceinline__ unsigned fkey(float f) {
    unsigned u = __float_as_uint(f);
    return (u & 0x80000000u) ? ~u : (u | 0x80000000u);
}

__device__ __forceinline__ unsigned tf32_of(float f) {
    unsigned u;
    asm("cvt.rna.tf32.f32 %0, %1;" : "=r"(u) : "f"(f));
    return u;
}

// ---------------- shared init (before fork) -------------------------------------
__global__ void k_init(int n) {
    int i = blockIdx.x * blockDim.x + threadIdx.x;
    if (i < 65536) g_h16[i] = 0u;
    if (i < n) g_deg[i] = 0;
    if (i == 0) g_ncand = 0;
}

// ---------------- stream A: top-k / GRU / GEMM ----------------------------------

// score[i] = x[i].p  + fused 16-bit-key histogram.  x is read-once: stream it (.cs)
__global__ void k_scorehist(const float* __restrict__ x, const float* __restrict__ p, int n) {
    int t = blockIdx.x * blockDim.x + threadIdx.x;
    int w = t >> 5, lane = t & 31;
    if (w >= n) return;
    float4 a = __ldcs(&((const float4*)x)[(size_t)w * 32 + lane]);
    float4 b = ((const float4*)p)[lane];
    float s = a.x * b.x + a.y * b.y + a.z * b.z + a.w * b.w;
    #pragma unroll
    for (int o = 16; o; o >>= 1) s += __shfl_down_sync(0xffffffffu, s, o);
    if (lane == 0) {
        g_score[w] = s;
        atomicAdd(&g_h16[fkey(s) >> 16], 1u);
    }
}

// single-block suffix scan over 65536 bins -> exact 16-bit threshold bin
__global__ void k_scan16() {
    __shared__ unsigned part[1024];
    int tid = threadIdx.x;
    unsigned sum = 0;
    int base = tid * 64;
    #pragma unroll 8
    for (int i = 0; i < 64; i++) sum += g_h16[base + i];
    part[tid] = sum;
    __syncthreads();
    #pragma unroll
    for (int o = 1; o < 1024; o <<= 1) {
        unsigned t2 = (tid + o < 1024) ? part[tid + o] : 0u;
        __syncthreads();
        part[tid] += t2;
        __syncthreads();
    }
    unsigned here  = part[tid];
    unsigned above = (tid < 1023) ? part[tid + 1] : 0u;
    if (here >= TOPK && above < TOPK) {
        unsigned cum = above;
        for (int i = 63; i >= 0; i--) {
            cum += g_h16[base + i];
            if (cum >= TOPK) { g_thresh = ((unsigned)(base + i)) << 16; break; }
        }
    }
}

__global__ void k_compact(int n) {
    unsigned T = g_thresh;
    int i = blockIdx.x * blockDim.x + threadIdx.x;
    if (i >= n) return;
    float s = g_score[i];
    unsigned u = fkey(s);
    if (u >= T) {
        int pos = atomicAdd(&g_ncand, 1);
        if (pos < CANDCAP) {
            g_cand_idx[pos] = i;
            g_cand_key[pos] = u;
            g_cand_val[pos] = s;
        }
    }
}

// fused: rank (jax tie-break) + ||p|| + x_tilde gather + GRU cell
__global__ void k_grurank(const float* __restrict__ x, const float* __restrict__ p,
                          const float* __restrict__ Wih, const float* __restrict__ Whh,
                          const float* __restrict__ bih, const float* __restrict__ bhh,
                          const float* __restrict__ W0) {
    int j = blockIdx.x, d = threadIdx.x;
    __shared__ float xt[D], h0[D];
    __shared__ float red[4];
    __shared__ int   perm_s;
    __shared__ float tsc_s;

    float v = p[d]; v *= v;
    #pragma unroll
    for (int o = 16; o; o >>= 1) v += __shfl_down_sync(0xffffffffu, v, o);
    if ((d & 31) == 0) red[d >> 5] = v;
    __syncthreads();
    float pn = sqrtf(red[0] + red[1] + red[2] + red[3]);

    int nc = g_ncand;
    if (nc > CANDCAP) nc = CANDCAP;
    for (int c = d; c < nc; c += D) {
        unsigned uc = g_cand_key[c];
        int ic = g_cand_idx[c];
        int rank = 0;
        for (int o = 0; o < nc; o++) {
            unsigned uo = g_cand_key[o];
            rank += (uo > uc) || (uo == uc && g_cand_idx[o] < ic);
        }
        if (rank == j) { perm_s = ic; tsc_s = g_cand_val[c] / pn; }
    }
    __syncthreads();

    float tj = tanhf(tsc_s);
    xt[d] = x[(size_t)perm_s * D + d] * tj;
    h0[d] = W0[j * D + d];
    __syncthreads();

    float ir = bih[d], iz = bih[D + d], inn = bih[2 * D + d];
    float hr = bhh[d], hz = bhh[D + d], hn = bhh[2 * D + d];
    const float* wr = &Wih[(size_t)d * D];
    const float* wz = &Wih[(size_t)(D + d) * D];
    const float* wn = &Wih[(size_t)(2 * D + d) * D];
    const float* vr = &Whh[(size_t)d * D];
    const float* vz = &Whh[(size_t)(D + d) * D];
    const float* vn = &Whh[(size_t)(2 * D + d) * D];
    #pragma unroll 4
    for (int k = 0; k < D; k++) {
        float xk = xt[k], hk = h0[k];
        ir  = fmaf(xk, wr[k], ir);
        iz  = fmaf(xk, wz[k], iz);
        inn = fmaf(xk, wn[k], inn);
        hr  = fmaf(hk, vr[k], hr);
        hz  = fmaf(hk, vz[k], hz);
        hn  = fmaf(hk, vn[k], hn);
    }
    float r  = 1.f / (1.f + expf(-(ir + hr)));
    float z  = 1.f / (1.f + expf(-(iz + hz)));
    float nn = tanhf(inn + r * hn);
    g_W[j * D + d] = (1.f - z) * nn + z * h0[d];
}

// tf32 tensor-core GEMM: yh = half((x @ W) * dinv[row]).  x streamed (.cs).
__global__ void __launch_bounds__(256) k_gemm_tf32(const float* __restrict__ x, int n) {
    __shared__ float As[128][36];
    __shared__ float Bs[32][136];

    int tid  = threadIdx.x;
    int wid  = tid >> 5;
    int lane = tid & 31;
    int gid  = lane >> 2;
    int tig  = lane & 3;
    int warp_m = wid >> 1;
    int warp_n = wid & 1;
    int row_blk = blockIdx.x * 128;

    float acc[2][8][4];
    #pragma unroll
    for (int m = 0; m < 2; m++)
        #pragma unroll
        for (int nt = 0; nt < 8; nt++)
            #pragma unroll
            for (int j = 0; j < 4; j++) acc[m][nt][j] = 0.f;

    const float4* x4 = (const float4*)x;
    const float4* w4 = (const float4*)g_W;

    for (int k0 = 0; k0 < 128; k0 += 32) {
        #pragma unroll
        for (int it = 0; it < 4; it++) {
            int id = tid + it * 256;
            int r = id >> 3, c4 = id & 7;
            float4 v = make_float4(0.f, 0.f, 0.f, 0.f);
            int gr = row_blk + r;
            if (gr < n) v = __ldcs(&x4[(size_t)gr * 32 + (k0 >> 2) + c4]);
            float4 t = make_float4(__uint_as_float(tf32_of(v.x)), __uint_as_float(tf32_of(v.y)),
                                   __uint_as_float(tf32_of(v.z)), __uint_as_float(tf32_of(v.w)));
            *(float4*)&As[r][c4 * 4] = t;
        }
        #pragma unroll
        for (int it = 0; it < 4; it++) {
            int id = tid + it * 256;
            int kr = id >> 5, c4 = id & 31;
            float4 v = w4[(size_t)(k0 + kr) * 32 + c4];
            float4 t = make_float4(__uint_as_float(tf32_of(v.x)), __uint_as_float(tf32_of(v.y)),
                                   __uint_as_float(tf32_of(v.z)), __uint_as_float(tf32_of(v.w)));
            *(float4*)&Bs[kr][c4 * 4] = t;
        }
        __syncthreads();

        #pragma unroll
        for (int kk = 0; kk < 32; kk += 8) {
            unsigned a[2][4], b[8][2];
            #pragma unroll
            for (int m = 0; m < 2; m++) {
                int rb = warp_m * 32 + m * 16;
                a[m][0] = __float_as_uint(As[rb + gid][kk + tig]);
                a[m][1] = __float_as_uint(As[rb + gid + 8][kk + tig]);
                a[m][2] = __float_as_uint(As[rb + gid][kk + tig + 4]);
                a[m][3] = __float_as_uint(As[rb + gid + 8][kk + tig + 4]);
            }
            #pragma unroll
            for (int nt = 0; nt < 8; nt++) {
                int cb = warp_n * 64 + nt * 8 + gid;
                b[nt][0] = __float_as_uint(Bs[kk + tig][cb]);
                b[nt][1] = __float_as_uint(Bs[kk + tig + 4][cb]);
            }
            #pragma unroll
            for (int m = 0; m < 2; m++)
                #pragma unroll
                for (int nt = 0; nt < 8; nt++) {
                    asm volatile(
                        "mma.sync.aligned.m16n8k8.row.col.f32.tf32.tf32.f32 "
                        "{%0,%1,%2,%3}, {%4,%5,%6,%7}, {%8,%9}, {%0,%1,%2,%3};"
                        : "+f"(acc[m][nt][0]), "+f"(acc[m][nt][1]),
                          "+f"(acc[m][nt][2]), "+f"(acc[m][nt][3])
                        : "r"(a[m][0]), "r"(a[m][1]), "r"(a[m][2]), "r"(a[m][3]),
                          "r"(b[nt][0]), "r"(b[nt][1]));
                }
        }
        __syncthreads();
    }

    #pragma unroll
    for (int m = 0; m < 2; m++) {
        int r0 = row_blk + warp_m * 32 + m * 16 + gid;
        int r1 = r0 + 8;
        float d0 = (r0 < n) ? g_dinv[r0] : 0.f;
        float d1 = (r1 < n) ? g_dinv[r1] : 0.f;
        #pragma unroll
        for (int nt = 0; nt < 8; nt++) {
            int col = warp_n * 64 + nt * 8 + 2 * tig;
            if (r0 < n)
                g_yh[(size_t)r0 * 64 + (col >> 1)] =
                    __floats2half2_rn(acc[m][nt][0] * d0, acc[m][nt][1] * d0);
            if (r1 < n)
                g_yh[(size_t)r1 * 64 + (col >> 1)] =
                    __floats2half2_rn(acc[m][nt][2] * d1, acc[m][nt][3] * d1);
        }
    }
}

// ---------------- stream B: graph structure (deterministic scan offsets) ---------

__global__ void k_deg(const int* __restrict__ col, int E) {
    int e = blockIdx.x * blockDim.x + threadIdx.x;
    if (e < E) atomicAdd(&g_deg[col[e]], 1);
}

__global__ void k_scan1(int n) {
    __shared__ int sh[SCAN_CHUNK];
    int i = blockIdx.x * SCAN_CHUNK + threadIdx.x;
    int v = (i < n) ? g_deg[i] : 0;
    sh[threadIdx.x] = v;
    __syncthreads();
    #pragma unroll
    for (int o = 1; o < SCAN_CHUNK; o <<= 1) {
        int t = (threadIdx.x >= o) ? sh[threadIdx.x - o] : 0;
        __syncthreads();
        sh[threadIdx.x] += t;
        __syncthreads();
    }
    if (i < n) g_off[i] = sh[threadIdx.x] - v;
    if (threadIdx.x == SCAN_CHUNK - 1) g_bsum[blockIdx.x] = sh[SCAN_CHUNK - 1];
}

__global__ void k_scan2(int nb) {
    __shared__ int sh[1024];
    int v = (threadIdx.x < nb) ? g_bsum[threadIdx.x] : 0;
    sh[threadIdx.x] = v;
    __syncthreads();
    #pragma unroll
    for (int o = 1; o < 1024; o <<= 1) {
        int t = (threadIdx.x >= o) ? sh[threadIdx.x - o] : 0;
        __syncthreads();
        sh[threadIdx.x] += t;
        __syncthreads();
    }
    if (threadIdx.x < nb) g_bsum[threadIdx.x] = sh[threadIdx.x] - v;
}

// finalize offsets + cur + dinv (fused)
__global__ void k_scan3(int n, int E) {
    int i = blockIdx.x * blockDim.x + threadIdx.x;
    if (i < n) {
        int o = g_off[i] + g_bsum[i >> 10];
        g_off[i] = o;
        g_cur[i] = o;
        g_dinv[i] = rsqrtf((float)g_deg[i] + 1.0f);
    }
    if (i == n) g_off[n] = E;
}

__global__ void k_sortedge(const int* __restrict__ row, const int* __restrict__ col, int E) {
    int e = blockIdx.x * blockDim.x + threadIdx.x;
    if (e < E) {
        int c = col[e];
        int pos = atomicAdd(&g_cur[c], 1);
        g_er[pos] = row[e];
    }
}

// ---------------- joined: fused aggregate ----------------------------------------
// out[c] = normalize(relu( sum_{e in seg(c)} y[row_e] + y[c] ))  (outer dinv[c] cancels)
// TWO warps per node (alternating 32-edge blocks) -> 2x outstanding gathers.
// Merge partials via shared memory; even warp finalizes.
__global__ void __launch_bounds__(256) k_agg2(int n, float4* __restrict__ out4) {
    __shared__ float smrg[4][32][4];      // 4 nodes per 256-thread block
    int gw = (blockIdx.x * blockDim.x + threadIdx.x) >> 5;   // global warp id
    int w = gw >> 1;                       // node id
    int half = gw & 1;                     // 0 or 1
    int lane = threadIdx.x & 31;
    int pair = (threadIdx.x >> 6);         // node slot within block: 0..3

    float4 acc = make_float4(0.f, 0.f, 0.f, 0.f);
    const uint2* yv = (const uint2*)g_yh;

    if (w < n) {
        int beg = g_off[w], end = g_off[w + 1];
        if (half == 0) {                   // self-loop term y[c]
            uint2 su = __ldg(&yv[(size_t)w * 32 + lane]);
            float2 f0 = __half22float2(*(__half2*)&su.x);
            float2 f1 = __half22float2(*(__half2*)&su.y);
            acc = make_float4(f0.x, f0.y, f1.x, f1.y);
        }
        // alternating 32-edge blocks: half h takes base = beg + (2k+h)*32
        for (int base = beg + half * 32; base < end; base += 64) {
            int e = base + lane;
            int r = (e < end) ? __ldcs(&g_er[e]) : 0;
            int cnt = min(end - base, 32);
            int j = 0;
            #pragma unroll 4
            for (; j + 1 < cnt; j += 2) {
                int rr0 = __shfl_sync(0xffffffffu, r, j);
                int rr1 = __shfl_sync(0xffffffffu, r, j + 1);
                uint2 u0 = __ldg(&yv[(size_t)rr0 * 32 + lane]);
                uint2 u1 = __ldg(&yv[(size_t)rr1 * 32 + lane]);
                __half2 s0 = __hadd2(*(__half2*)&u0.x, *(__half2*)&u1.x);
                __half2 s1 = __hadd2(*(__half2*)&u0.y, *(__half2*)&u1.y);
                float2 a = __half22float2(s0), b = __half22float2(s1);
                acc.x += a.x; acc.y += a.y; acc.z += b.x; acc.w += b.y;
            }
            if (j < cnt) {
                int rr = __shfl_sync(0xffffffffu, r, j);
                uint2 u = __ldg(&yv[(size_t)rr * 32 + lane]);
                float2 a = __half22float2(*(__half2*)&u.x);
                float2 b = __half22float2(*(__half2*)&u.y);
                acc.x += a.x; acc.y += a.y; acc.z += b.x; acc.w += b.y;
            }
        }
    }
    // merge the two halves through smem
    if (half == 1) {
        smrg[pair][lane][0] = acc.x;
        smrg[pair][lane][1] = acc.y;
        smrg[pair][lane][2] = acc.z;
        smrg[pair][lane][3] = acc.w;
    }
    __syncthreads();
    if (half == 0 && w < n) {
        acc.x += smrg[pair][lane][0];
        acc.y += smrg[pair][lane][1];
        acc.z += smrg[pair][lane][2];
        acc.w += smrg[pair][lane][3];
        acc.x = fmaxf(acc.x, 0.f);
        acc.y = fmaxf(acc.y, 0.f);
        acc.z = fmaxf(acc.z, 0.f);
        acc.w = fmaxf(acc.w, 0.f);
        float ss = acc.x * acc.x + acc.y * acc.y + acc.z * acc.z + acc.w * acc.w;
        #pragma unroll
        for (int o = 16; o; o >>= 1) ss += __shfl_xor_sync(0xffffffffu, ss, o);
        float inv = 1.f / fmaxf(sqrtf(ss), 1e-12f);
        acc.x *= inv; acc.y *= inv; acc.z *= inv; acc.w *= inv;
        __stcs(&out4[(size_t)w * 32 + lane], acc);
    }
}

// ---------------- launch ------------------------------------------------------------
extern "C" void kernel_launch(void* const* d_in, const int* in_sizes, int n_in,
                              void* d_out, int out_size) {
    const float* H   = (const float*)d_in[0];
    const int*   el  = (const int*)d_in[1];
    const float* p   = (const float*)d_in[2];
    const float* Wih = (const float*)d_in[3];
    const float* Whh = (const float*)d_in[4];
    const float* bih = (const float*)d_in[5];
    const float* bhh = (const float*)d_in[6];
    const float* W0  = (const float*)d_in[7];
    float4* out4 = (float4*)d_out;

    int N = in_sizes[0] / (3 * D);
    int E = in_sizes[1] / 6;
    const int* row = el;
    const int* col = el + E;
    int nb = (N + SCAN_CHUNK - 1) / SCAN_CHUNK;

    cudaStream_t sB;
    cudaEvent_t evF, evD, evJ;
    cudaStreamCreateWithFlags(&sB, cudaStreamNonBlocking);
    cudaEventCreateWithFlags(&evF, cudaEventDisableTiming);
    cudaEventCreateWithFlags(&evD, cudaEventDisableTiming);
    cudaEventCreateWithFlags(&evJ, cudaEventDisableTiming);

    // shared init, then fork
    int ig = (N > 65536 ? N : 65536);
    k_init<<<(ig + 255) / 256, 256>>>(N);
    cudaEventRecord(evF, 0);
    cudaStreamWaitEvent(sB, evF, 0);

    // ---- stream B: graph structure (deterministic offsets) ----
    k_deg<<<(E + 255) / 256, 256, 0, sB>>>(col, E);
    k_scan1<<<nb, SCAN_CHUNK, 0, sB>>>(N);
    k_scan2<<<1, 1024, 0, sB>>>(nb);
    k_scan3<<<(N + 256) / 256, 256, 0, sB>>>(N, E);
    cudaEventRecord(evD, sB);            // dinv ready
    k_sortedge<<<(E + 255) / 256, 256, 0, sB>>>(row, col, E);
    cudaEventRecord(evJ, sB);            // er ready

    // ---- stream A (default): top-k -> GRU -> GEMM ----
    k_scorehist<<<(N * 32 + 255) / 256, 256>>>(H, p, N);
    k_scan16<<<1, 1024>>>();
    k_compact<<<(N + 255) / 256, 256>>>(N);
    k_grurank<<<D, D>>>(H, p, Wih, Whh, bih, bhh, W0);
    cudaStreamWaitEvent(0, evD, 0);      // GEMM needs dinv; overlaps sortedge
    k_gemm_tf32<<<(N + 127) / 128, 256>>>(H, N);

    // join: agg needs yh (A) and off/er (B).  2 warps per node.
    cudaStreamWaitEvent(0, evJ, 0);
    k_agg2<<<((size_t)N * 64 + 255) / 256, 256>>>(N, out4);
}

// round 16
// speedup vs baseline: 1.1621x; 1.1621x over previous
#include <cuda_runtime.h>
#include <cuda_fp16.h>
#include <math.h>

#define D 128
#define MAXN 100000
#define MAXE 3200000
#define TOPK 128
#define CANDCAP 4096
#define SCAN_CHUNK 1024

// ---------------- scratch ----------------------------------------------------
__device__ float    g_score[MAXN];
__device__ unsigned g_h16[65536];
__device__ unsigned g_thresh;
__device__ int      g_ncand;
__device__ int      g_cand_idx[CANDCAP];
__device__ unsigned g_cand_key[CANDCAP];
__device__ float    g_cand_val[CANDCAP];
__device__ float    g_W[D * D];
__device__ __half2  g_yh[(size_t)MAXN * 64];   // y = (x@W)*dinv[row], fp16
__device__ float    g_dinv[MAXN];
__device__ int      g_deg[MAXN];
__device__ int      g_off[MAXN + 1];
__device__ int      g_cur[MAXN];
__device__ int      g_bsum[1024];
__device__ int      g_er[MAXE];

__device__ __forceinline__ unsigned fkey(float f) {
    unsigned u = __float_as_uint(f);
    return (u & 0x80000000u) ? ~u : (u | 0x80000000u);
}

__device__ __forceinline__ unsigned tf32_of(float f) {
    unsigned u;
    asm("cvt.rna.tf32.f32 %0, %1;" : "=r"(u) : "f"(f));
    return u;
}

// ---------------- shared init (before fork) -------------------------------------
__global__ void k_init(int n) {
    int i = blockIdx.x * blockDim.x + threadIdx.x;
    if (i < 65536) g_h16[i] = 0u;
    if (i < n) g_deg[i] = 0;
    if (i == 0) g_ncand = 0;
}

// ---------------- stream A: top-k / GRU / GEMM ----------------------------------

__global__ void k_scorehist(const float* __restrict__ x, const float* __restrict__ p, int n) {
    int t = blockIdx.x * blockDim.x + threadIdx.x;
    int w = t >> 5, lane = t & 31;
    if (w >= n) return;
    float4 a = __ldcs(&((const float4*)x)[(size_t)w * 32 + lane]);
    float4 b = ((const float4*)p)[lane];
    float s = a.x * b.x + a.y * b.y + a.z * b.z + a.w * b.w;
    #pragma unroll
    for (int o = 16; o; o >>= 1) s += __shfl_down_sync(0xffffffffu, s, o);
    if (lane == 0) {
        g_score[w] = s;
        atomicAdd(&g_h16[fkey(s) >> 16], 1u);
    }
}

__global__ void k_scan16() {
    __shared__ unsigned part[1024];
    int tid = threadIdx.x;
    unsigned sum = 0;
    int base = tid * 64;
    #pragma unroll 8
    for (int i = 0; i < 64; i++) sum += g_h16[base + i];
    part[tid] = sum;
    __syncthreads();
    #pragma unroll
    for (int o = 1; o < 1024; o <<= 1) {
        unsigned t2 = (tid + o < 1024) ? part[tid + o] : 0u;
        __syncthreads();
        part[tid] += t2;
        __syncthreads();
    }
    unsigned here  = part[tid];
    unsigned above = (tid < 1023) ? part[tid + 1] : 0u;
    if (here >= TOPK && above < TOPK) {
        unsigned cum = above;
        for (int i = 63; i >= 0; i--) {
            cum += g_h16[base + i];
            if (cum >= TOPK) { g_thresh = ((unsigned)(base + i)) << 16; break; }
        }
    }
}

__global__ void k_compact(int n) {
    unsigned T = g_thresh;
    int i = blockIdx.x * blockDim.x + threadIdx.x;
    if (i >= n) return;
    float s = g_score[i];
    unsigned u = fkey(s);
    if (u >= T) {
        int pos = atomicAdd(&g_ncand, 1);
        if (pos < CANDCAP) {
            g_cand_idx[pos] = i;
            g_cand_key[pos] = u;
            g_cand_val[pos] = s;
        }
    }
}

__global__ void k_grurank(const float* __restrict__ x, const float* __restrict__ p,
                          const float* __restrict__ Wih, const float* __restrict__ Whh,
                          const float* __restrict__ bih, const float* __restrict__ bhh,
                          const float* __restrict__ W0) {
    int j = blockIdx.x, d = threadIdx.x;
    __shared__ float xt[D], h0[D];
    __shared__ float red[4];
    __shared__ int   perm_s;
    __shared__ float tsc_s;

    float v = p[d]; v *= v;
    #pragma unroll
    for (int o = 16; o; o >>= 1) v += __shfl_down_sync(0xffffffffu, v, o);
    if ((d & 31) == 0) red[d >> 5] = v;
    __syncthreads();
    float pn = sqrtf(red[0] + red[1] + red[2] + red[3]);

    int nc = g_ncand;
    if (nc > CANDCAP) nc = CANDCAP;
    for (int c = d; c < nc; c += D) {
        unsigned uc = g_cand_key[c];
        int ic = g_cand_idx[c];
        int rank = 0;
        for (int o = 0; o < nc; o++) {
            unsigned uo = g_cand_key[o];
            rank += (uo > uc) || (uo == uc && g_cand_idx[o] < ic);
        }
        if (rank == j) { perm_s = ic; tsc_s = g_cand_val[c] / pn; }
    }
    __syncthreads();

    float tj = tanhf(tsc_s);
    xt[d] = x[(size_t)perm_s * D + d] * tj;
    h0[d] = W0[j * D + d];
    __syncthreads();

    float ir = bih[d], iz = bih[D + d], inn = bih[2 * D + d];
    float hr = bhh[d], hz = bhh[D + d], hn = bhh[2 * D + d];
    const float* wr = &Wih[(size_t)d * D];
    const float* wz = &Wih[(size_t)(D + d) * D];
    const float* wn = &Wih[(size_t)(2 * D + d) * D];
    const float* vr = &Whh[(size_t)d * D];
    const float* vz = &Whh[(size_t)(D + d) * D];
    const float* vn = &Whh[(size_t)(2 * D + d) * D];
    #pragma unroll 4
    for (int k = 0; k < D; k++) {
        float xk = xt[k], hk = h0[k];
        ir  = fmaf(xk, wr[k], ir);
        iz  = fmaf(xk, wz[k], iz);
        inn = fmaf(xk, wn[k], inn);
        hr  = fmaf(hk, vr[k], hr);
        hz  = fmaf(hk, vz[k], hz);
        hn  = fmaf(hk, vn[k], hn);
    }
    float r  = 1.f / (1.f + expf(-(ir + hr)));
    float z  = 1.f / (1.f + expf(-(iz + hz)));
    float nn = tanhf(inn + r * hn);
    g_W[j * D + d] = (1.f - z) * nn + z * h0[d];
}

__global__ void __launch_bounds__(256) k_gemm_tf32(const float* __restrict__ x, int n) {
    __shared__ float As[128][36];
    __shared__ float Bs[32][136];

    int tid  = threadIdx.x;
    int wid  = tid >> 5;
    int lane = tid & 31;
    int gid  = lane >> 2;
    int tig  = lane & 3;
    int warp_m = wid >> 1;
    int warp_n = wid & 1;
    int row_blk = blockIdx.x * 128;

    float acc[2][8][4];
    #pragma unroll
    for (int m = 0; m < 2; m++)
        #pragma unroll
        for (int nt = 0; nt < 8; nt++)
            #pragma unroll
            for (int j = 0; j < 4; j++) acc[m][nt][j] = 0.f;

    const float4* x4 = (const float4*)x;
    const float4* w4 = (const float4*)g_W;

    for (int k0 = 0; k0 < 128; k0 += 32) {
        #pragma unroll
        for (int it = 0; it < 4; it++) {
            int id = tid + it * 256;
            int r = id >> 3, c4 = id & 7;
            float4 v = make_float4(0.f, 0.f, 0.f, 0.f);
            int gr = row_blk + r;
            if (gr < n) v = __ldcs(&x4[(size_t)gr * 32 + (k0 >> 2) + c4]);
            float4 t = make_float4(__uint_as_float(tf32_of(v.x)), __uint_as_float(tf32_of(v.y)),
                                   __uint_as_float(tf32_of(v.z)), __uint_as_float(tf32_of(v.w)));
            *(float4*)&As[r][c4 * 4] = t;
        }
        #pragma unroll
        for (int it = 0; it < 4; it++) {
            int id = tid + it * 256;
            int kr = id >> 5, c4 = id & 31;
            float4 v = w4[(size_t)(k0 + kr) * 32 + c4];
            float4 t = make_float4(__uint_as_float(tf32_of(v.x)), __uint_as_float(tf32_of(v.y)),
                                   __uint_as_float(tf32_of(v.z)), __uint_as_float(tf32_of(v.w)));
            *(float4*)&Bs[kr][c4 * 4] = t;
        }
        __syncthreads();

        #pragma unroll
        for (int kk = 0; kk < 32; kk += 8) {
            unsigned a[2][4], b[8][2];
            #pragma unroll
            for (int m = 0; m < 2; m++) {
                int rb = warp_m * 32 + m * 16;
                a[m][0] = __float_as_uint(As[rb + gid][kk + tig]);
                a[m][1] = __float_as_uint(As[rb + gid + 8][kk + tig]);
                a[m][2] = __float_as_uint(As[rb + gid][kk + tig + 4]);
                a[m][3] = __float_as_uint(As[rb + gid + 8][kk + tig + 4]);
            }
            #pragma unroll
            for (int nt = 0; nt < 8; nt++) {
                int cb = warp_n * 64 + nt * 8 + gid;
                b[nt][0] = __float_as_uint(Bs[kk + tig][cb]);
                b[nt][1] = __float_as_uint(Bs[kk + tig + 4][cb]);
            }
            #pragma unroll
            for (int m = 0; m < 2; m++)
                #pragma unroll
                for (int nt = 0; nt < 8; nt++) {
                    asm volatile(
                        "mma.sync.aligned.m16n8k8.row.col.f32.tf32.tf32.f32 "
                        "{%0,%1,%2,%3}, {%4,%5,%6,%7}, {%8,%9}, {%0,%1,%2,%3};"
                        : "+f"(acc[m][nt][0]), "+f"(acc[m][nt][1]),
                          "+f"(acc[m][nt][2]), "+f"(acc[m][nt][3])
                        : "r"(a[m][0]), "r"(a[m][1]), "r"(a[m][2]), "r"(a[m][3]),
                          "r"(b[nt][0]), "r"(b[nt][1]));
                }
        }
        __syncthreads();
    }

    #pragma unroll
    for (int m = 0; m < 2; m++) {
        int r0 = row_blk + warp_m * 32 + m * 16 + gid;
        int r1 = r0 + 8;
        float d0 = (r0 < n) ? g_dinv[r0] : 0.f;
        float d1 = (r1 < n) ? g_dinv[r1] : 0.f;
        #pragma unroll
        for (int nt = 0; nt < 8; nt++) {
            int col = warp_n * 64 + nt * 8 + 2 * tig;
            if (r0 < n)
                g_yh[(size_t)r0 * 64 + (col >> 1)] =
                    __floats2half2_rn(acc[m][nt][0] * d0, acc[m][nt][1] * d0);
            if (r1 < n)
                g_yh[(size_t)r1 * 64 + (col >> 1)] =
                    __floats2half2_rn(acc[m][nt][2] * d1, acc[m][nt][3] * d1);
        }
    }
}

// ---------------- stream B: graph structure (deterministic scan offsets) ---------

__global__ void k_deg(const int* __restrict__ col, int E) {
    int e = blockIdx.x * blockDim.x + threadIdx.x;
    if (e < E) atomicAdd(&g_deg[col[e]], 1);
}

__global__ void k_scan1(int n) {
    __shared__ int sh[SCAN_CHUNK];
    int i = blockIdx.x * SCAN_CHUNK + threadIdx.x;
    int v = (i < n) ? g_deg[i] : 0;
    sh[threadIdx.x] = v;
    __syncthreads();
    #pragma unroll
    for (int o = 1; o < SCAN_CHUNK; o <<= 1) {
        int t = (threadIdx.x >= o) ? sh[threadIdx.x - o] : 0;
        __syncthreads();
        sh[threadIdx.x] += t;
        __syncthreads();
    }
    if (i < n) g_off[i] = sh[threadIdx.x] - v;
    if (threadIdx.x == SCAN_CHUNK - 1) g_bsum[blockIdx.x] = sh[SCAN_CHUNK - 1];
}

__global__ void k_scan2(int nb) {
    __shared__ int sh[1024];
    int v = (threadIdx.x < nb) ? g_bsum[threadIdx.x] : 0;
    sh[threadIdx.x] = v;
    __syncthreads();
    #pragma unroll
    for (int o = 1; o < 1024; o <<= 1) {
        int t = (threadIdx.x >= o) ? sh[threadIdx.x - o] : 0;
        __syncthreads();
        sh[threadIdx.x] += t;
        __syncthreads();
    }
    if (threadIdx.x < nb) g_bsum[threadIdx.x] = sh[threadIdx.x] - v;
}

__global__ void k_scan3(int n, int E) {
    int i = blockIdx.x * blockDim.x + threadIdx.x;
    if (i < n) {
        int o = g_off[i] + g_bsum[i >> 10];
        g_off[i] = o;
        g_cur[i] = o;
        g_dinv[i] = rsqrtf((float)g_deg[i] + 1.0f);
    }
    if (i == n) g_off[n] = E;
}

__global__ void k_sortedge(const int* __restrict__ row, const int* __restrict__ col, int E) {
    int e = blockIdx.x * blockDim.x + threadIdx.x;
    if (e < E) {
        int c = col[e];
        int pos = atomicAdd(&g_cur[c], 1);
        g_er[pos] = row[e];
    }
}

// ---------------- joined: fused aggregate ----------------------------------------
// out[c] = normalize(relu( sum_{e in seg(c)} y[row_e] + y[c] ))  (outer dinv[c] cancels)
// Half-warp row ownership: 16 lanes x uint4 = 256B row; 2 edges per warp wave,
// HADD2-paired along the edge sequence (4 edges per inner iteration per warp).
__global__ void __launch_bounds__(256) k_agg(int n, float4* __restrict__ out4) {
    int w = (blockIdx.x * blockDim.x + threadIdx.x) >> 5;
    if (w >= n) return;
    int lane = threadIdx.x & 31;
    int half = lane >> 4;          // 0 or 1
    int l15  = lane & 15;
    int beg = g_off[w], end = g_off[w + 1];
    const uint4* yv4 = (const uint4*)g_yh;   // 16 uint4 per row

    float acc[8];
    #pragma unroll
    for (int k = 0; k < 8; k++) acc[k] = 0.f;

    if (half == 0) {               // self-loop term y[c]
        uint4 su = __ldg(&yv4[(size_t)w * 16 + l15]);
        __half2* hp = (__half2*)&su;
        #pragma unroll
        for (int k2 = 0; k2 < 4; k2++) {
            float2 f = __half22float2(hp[k2]);
            acc[2 * k2]     = f.x;
            acc[2 * k2 + 1] = f.y;
        }
    }

    for (int base = beg; base < end; base += 32) {
        int e = base + lane;
        int r = (e < end) ? __ldcs(&g_er[e]) : 0;
        int cnt = min(end - base, 32);
        int q = 0;
        // paired: half h takes edges q+h and q+2+h (4 edges per iteration)
        #pragma unroll 4
        for (; q + 3 < cnt; q += 4) {
            int rr0 = __shfl_sync(0xffffffffu, r, q + half);
            int rr1 = __shfl_sync(0xffffffffu, r, q + 2 + half);
            uint4 u0 = __ldg(&yv4[(size_t)rr0 * 16 + l15]);
            uint4 u1 = __ldg(&yv4[(size_t)rr1 * 16 + l15]);
            __half2* h0 = (__half2*)&u0;
            __half2* h1 = (__half2*)&u1;
            #pragma unroll
            for (int k2 = 0; k2 < 4; k2++) {
                __half2 s = __hadd2(h0[k2], h1[k2]);
                float2 f = __half22float2(s);
                acc[2 * k2]     += f.x;
                acc[2 * k2 + 1] += f.y;
            }
        }
        // 2-edge step: half h takes edge q+h
        if (q + 1 < cnt) {
            int rr = __shfl_sync(0xffffffffu, r, q + half);
            uint4 u = __ldg(&yv4[(size_t)rr * 16 + l15]);
            __half2* hp = (__half2*)&u;
            #pragma unroll
            for (int k2 = 0; k2 < 4; k2++) {
                float2 f = __half22float2(hp[k2]);
                acc[2 * k2]     += f.x;
                acc[2 * k2 + 1] += f.y;
            }
            q += 2;
        }
        // single leftover: half 0 only
        if (q < cnt) {
            int rr = __shfl_sync(0xffffffffu, r, q);
            if (half == 0) {
                uint4 u = __ldg(&yv4[(size_t)rr * 16 + l15]);
                __half2* hp = (__half2*)&u;
                #pragma unroll
                for (int k2 = 0; k2 < 4; k2++) {
                    float2 f = __half22float2(hp[k2]);
                    acc[2 * k2]     += f.x;
                    acc[2 * k2 + 1] += f.y;
                }
            }
        }
    }
    // merge halves, relu
    #pragma unroll
    for (int k = 0; k < 8; k++) {
        acc[k] += __shfl_down_sync(0xffffffffu, acc[k], 16);
        acc[k] = fmaxf(acc[k], 0.f);
    }
    float ss = 0.f;
    #pragma unroll
    for (int k = 0; k < 8; k++) ss += acc[k] * acc[k];
    #pragma unroll
    for (int o = 8; o; o >>= 1) ss += __shfl_xor_sync(0xffffffffu, ss, o);
    float inv = 1.f / fmaxf(sqrtf(ss), 1e-12f);
    if (half == 0) {
        float4 o0 = make_float4(acc[0] * inv, acc[1] * inv, acc[2] * inv, acc[3] * inv);
        float4 o1 = make_float4(acc[4] * inv, acc[5] * inv, acc[6] * inv, acc[7] * inv);
        __stcs(&out4[(size_t)w * 32 + l15 * 2], o0);
        __stcs(&out4[(size_t)w * 32 + l15 * 2 + 1], o1);
    }
}

// ---------------- launch ------------------------------------------------------------
extern "C" void kernel_launch(void* const* d_in, const int* in_sizes, int n_in,
                              void* d_out, int out_size) {
    const float* H   = (const float*)d_in[0];
    const int*   el  = (const int*)d_in[1];
    const float* p   = (const float*)d_in[2];
    const float* Wih = (const float*)d_in[3];
    const float* Whh = (const float*)d_in[4];
    const float* bih = (const float*)d_in[5];
    const float* bhh = (const float*)d_in[6];
    const float* W0  = (const float*)d_in[7];
    float4* out4 = (float4*)d_out;

    int N = in_sizes[0] / (3 * D);
    int E = in_sizes[1] / 6;
    const int* row = el;
    const int* col = el + E;
    int nb = (N + SCAN_CHUNK - 1) / SCAN_CHUNK;

    cudaStream_t sB;
    cudaEvent_t evF, evD, evJ;
    cudaStreamCreateWithFlags(&sB, cudaStreamNonBlocking);
    cudaEventCreateWithFlags(&evF, cudaEventDisableTiming);
    cudaEventCreateWithFlags(&evD, cudaEventDisableTiming);
    cudaEventCreateWithFlags(&evJ, cudaEventDisableTiming);

    // shared init, then fork
    int ig = (N > 65536 ? N : 65536);
    k_init<<<(ig + 255) / 256, 256>>>(N);
    cudaEventRecord(evF, 0);
    cudaStreamWaitEvent(sB, evF, 0);

    // ---- stream B: graph structure (deterministic offsets) ----
    k_deg<<<(E + 255) / 256, 256, 0, sB>>>(col, E);
    k_scan1<<<nb, SCAN_CHUNK, 0, sB>>>(N);
    k_scan2<<<1, 1024, 0, sB>>>(nb);
    k_scan3<<<(N + 256) / 256, 256, 0, sB>>>(N, E);
    cudaEventRecord(evD, sB);            // dinv ready
    k_sortedge<<<(E + 255) / 256, 256, 0, sB>>>(row, col, E);
    cudaEventRecord(evJ, sB);            // er ready

    // ---- stream A (default): top-k -> GRU -> GEMM ----
    k_scorehist<<<(N * 32 + 255) / 256, 256>>>(H, p, N);
    k_scan16<<<1, 1024>>>();
    k_compact<<<(N + 255) / 256, 256>>>(N);
    k_grurank<<<D, D>>>(H, p, Wih, Whh, bih, bhh, W0);
    cudaStreamWaitEvent(0, evD, 0);      // GEMM needs dinv; overlaps sortedge
    k_gemm_tf32<<<(N + 127) / 128, 256>>>(H, N);

    // join: agg needs yh (A) and off/er (B)
    cudaStreamWaitEvent(0, evJ, 0);
    k_agg<<<(N * 32 + 255) / 256, 256>>>(N, out4);
}